// round 2
// baseline (speedup 1.0000x reference)
#include <cuda_runtime.h>
#include <cuda_bf16.h>
#include <cstdint>

// ============================================================================
// Problem constants
// ============================================================================
#define NQ     6
#define DIM    64
#define NL     8
#define TILE   128           // batch rows per tile
#define KTOT   192           // [xhi | xlo | xhi]  vs  [Whi | Whi | Wlo]
#define KH     200           // padded halves per smem row (stride/16B = 25, odd -> LDSM conflict-free)
#define RSTRIDE (KH * 2)     // 400 bytes
#define GRIDB  296           // persistent CTAs (148 SMs x 2)

// Circuit constants built per-launch by qnn_build.
// Row 2j = Re(U[j][:]), row 2j+1 = Im(U[j][:])  (hi/lo bf16 split)
__device__ __align__(16) __nv_bfloat16 g_Whi[128 * 64];
__device__ __align__(16) __nv_bfloat16 g_Wlo[128 * 64];
__device__ __align__(16) float4 g_Mt[64];   // Mt[j] = {M[0][j],..,M[3][j]},  M = fc_w * Zsign^T
__device__ __align__(16) float4 g_fcb;

// ============================================================================
// PTX helpers (plain sm_103-legal: ldmatrix + mma.sync only)
// ============================================================================
__device__ __forceinline__ uint32_t smem_u32(const void* p) {
    uint32_t a;
    asm("{ .reg .u64 t; cvta.to.shared.u64 t, %1; cvt.u32.u64 %0, t; }" : "=r"(a) : "l"(p));
    return a;
}
__device__ __forceinline__ void ldsm_x4(uint32_t* r, uint32_t addr) {
    asm volatile("ldmatrix.sync.aligned.m8n8.x4.shared.b16 {%0,%1,%2,%3}, [%4];"
                 : "=r"(r[0]), "=r"(r[1]), "=r"(r[2]), "=r"(r[3]) : "r"(addr));
}
__device__ __forceinline__ void ldsm_x2(uint32_t* r, uint32_t addr) {
    asm volatile("ldmatrix.sync.aligned.m8n8.x2.shared.b16 {%0,%1}, [%2];"
                 : "=r"(r[0]), "=r"(r[1]) : "r"(addr));
}
__device__ __forceinline__ void mma16816(float* c, const uint32_t* a, const uint32_t* b) {
    asm volatile("mma.sync.aligned.m16n8k16.row.col.f32.bf16.bf16.f32 "
                 "{%0,%1,%2,%3}, {%4,%5,%6,%7}, {%8,%9}, {%0,%1,%2,%3};"
                 : "+f"(c[0]), "+f"(c[1]), "+f"(c[2]), "+f"(c[3])
                 : "r"(a[0]), "r"(a[1]), "r"(a[2]), "r"(a[3]), "r"(b[0]), "r"(b[1]));
}
__device__ __forceinline__ uint32_t pack_bf16(float x, float y) {
    __nv_bfloat162 h = __floats2bfloat162_rn(x, y);
    return *reinterpret_cast<uint32_t*>(&h);
}

// ============================================================================
// Kernel A: build U columns (one warp per basis column), emit Whi/Wlo/Mt/fcb.
// Each lane holds 2 complex amplitudes: amp = lane + 32*slot.
// qubit q acts on amplitude-index bit b = 5-q (qubit 0 = MSB).
// ============================================================================
__global__ void qnn_build(const float* __restrict__ weights,
                          const float* __restrict__ fc_w,
                          const float* __restrict__ fc_b) {
    const int w = blockIdx.x;     // basis column
    const int lane = threadIdx.x; // 32 threads

    float sr0 = (lane == w) ? 1.f : 0.f,      si0 = 0.f;
    float sr1 = (lane + 32 == w) ? 1.f : 0.f, si1 = 0.f;

    for (int l = 0; l < NL; l++) {
        for (int q = 0; q < NQ; q++) {
            const float* g = weights + (l * NQ + q) * 3;
            float phi = g[0], th = g[1], om = g[2];
            float st, ct; sincosf(0.5f * th, &st, &ct);
            float sa, ca; sincosf(0.5f * (phi + om), &sa, &ca);
            float sb, cb; sincosf(0.5f * (phi - om), &sb, &cb);
            float m00r =  ca * ct, m00i = -sa * ct;
            float m01r = -cb * st, m01i = -sb * st;
            float m10r =  cb * st, m10i = -sb * st;
            float m11r =  ca * ct, m11i =  sa * ct;
            int b = 5 - q;
            if (b == 5) {
                float nr0 = m00r*sr0 - m00i*si0 + m01r*sr1 - m01i*si1;
                float ni0 = m00r*si0 + m00i*sr0 + m01r*si1 + m01i*sr1;
                float nr1 = m10r*sr0 - m10i*si0 + m11r*sr1 - m11i*si1;
                float ni1 = m10r*si0 + m10i*sr0 + m11r*si1 + m11i*sr1;
                sr0 = nr0; si0 = ni0; sr1 = nr1; si1 = ni1;
            } else {
                int msk = 1 << b;
                int bit = (lane >> b) & 1;
                float dr = bit ? m11r : m00r, di = bit ? m11i : m00i;
                float orr = bit ? m10r : m01r, oi = bit ? m10i : m01i;
                float pr, pi, nr, ni;
                pr = __shfl_xor_sync(0xffffffffu, sr0, msk);
                pi = __shfl_xor_sync(0xffffffffu, si0, msk);
                nr = dr*sr0 - di*si0 + orr*pr - oi*pi;
                ni = dr*si0 + di*sr0 + orr*pi + oi*pr;
                sr0 = nr; si0 = ni;
                pr = __shfl_xor_sync(0xffffffffu, sr1, msk);
                pi = __shfl_xor_sync(0xffffffffu, si1, msk);
                nr = dr*sr1 - di*si1 + orr*pr - oi*pi;
                ni = dr*si1 + di*sr1 + orr*pi + oi*pr;
                sr1 = nr; si1 = ni;
            }
        }
        int r = (l % (NQ - 1)) + 1;
        for (int q = 0; q < NQ; q++) {
            int t = (q + r) % NQ;
            int bc = 5 - q, bt = 5 - t;
            if (bc == 5) {
                int m = 1 << bt;
                sr1 = __shfl_xor_sync(0xffffffffu, sr1, m);
                si1 = __shfl_xor_sync(0xffffffffu, si1, m);
            } else if (bt == 5) {
                if ((lane >> bc) & 1) {
                    float tmp;
                    tmp = sr0; sr0 = sr1; sr1 = tmp;
                    tmp = si0; si0 = si1; si1 = tmp;
                }
            } else {
                int m = 1 << bt;
                int ctrl = (lane >> bc) & 1;
                float pr, pi;
                pr = __shfl_xor_sync(0xffffffffu, sr0, m);
                pi = __shfl_xor_sync(0xffffffffu, si0, m);
                if (ctrl) { sr0 = pr; si0 = pi; }
                pr = __shfl_xor_sync(0xffffffffu, sr1, m);
                pi = __shfl_xor_sync(0xffffffffu, si1, m);
                if (ctrl) { sr1 = pr; si1 = pi; }
            }
        }
    }

    // Interleaved rows: wrow 2a = Re amp a, wrow 2a+1 = Im amp a; column w.
    auto store = [&](int row, float v) {
        __nv_bfloat16 h = __float2bfloat16(v);
        float hf = __bfloat162float(h);
        __nv_bfloat16 lo = __float2bfloat16(v - hf);
        g_Whi[row * 64 + w] = h;
        g_Wlo[row * 64 + w] = lo;
    };
    store(2 * lane,            sr0);
    store(2 * lane + 1,        si0);
    store(2 * (lane + 32),     sr1);
    store(2 * (lane + 32) + 1, si1);

    if (w == 0) {
        for (int s = 0; s < 2; s++) {
            int d = lane + 32 * s;
            float m[4];
            for (int c = 0; c < 4; c++) {
                float acc = 0.f;
                for (int i = 0; i < NQ; i++) {
                    int bit = (d >> (5 - i)) & 1;
                    acc += fc_w[c * NQ + i] * (bit ? -1.f : 1.f);
                }
                m[c] = acc;
            }
            g_Mt[d] = make_float4(m[0], m[1], m[2], m[3]);
        }
        if (lane == 0)
            g_fcb = make_float4(fc_b[0], fc_b[1], fc_b[2], fc_b[3]);
    }
}

// ============================================================================
// Kernel B: persistent, 128 rows/tile, HMMA 16816 bf16, K=192 fused split.
// smem: Mt (1KB) | INV (512B) | A [128][200h] | B [128][200h]
// ============================================================================
#define OF_MT   0
#define OF_INV  1024
#define OF_A    1536
#define OF_B    (OF_A + 128 * RSTRIDE)      // 1536 + 51200 = 52736
#define SMEM_BYTES (OF_B + 128 * RSTRIDE)   // 103936

__global__ void __launch_bounds__(128)
qnn_main(const float4* __restrict__ X, float4* __restrict__ out, int ntiles) {
    extern __shared__ char smc[];
    const uint32_t sm = smem_u32(smc);

    const int tid  = threadIdx.x;
    const int wid  = tid >> 5;
    const int lane = tid & 31;

    float* sINV = reinterpret_cast<float*>(smc + OF_INV);
    const float4* sMt = reinterpret_cast<const float4*>(smc + OF_MT);

    // ---- One-time staging: B = [Whi | Whi | Wlo] rows, Mt ----
    for (int idx = tid; idx < 128 * 96; idx += 128) {
        int wrow = idx / 96;
        int u    = idx - wrow * 96;      // u32 unit within row (2 halves)
        int kk   = u * 2;                // k index (even)
        const uint32_t* src = (kk < 128) ? reinterpret_cast<const uint32_t*>(g_Whi)
                                         : reinterpret_cast<const uint32_t*>(g_Wlo);
        uint32_t val = src[wrow * 32 + ((kk & 63) >> 1)];
        *reinterpret_cast<uint32_t*>(smc + OF_B + wrow * RSTRIDE + kk * 2) = val;
    }
    if (tid < 64) reinterpret_cast<float4*>(smc + OF_MT)[tid] = g_Mt[tid];
    const float4 fcb = g_fcb;
    __syncthreads();

    const int sub = lane >> 4, l16 = lane & 15;
    const int m0 = wid * 32;

    // ldmatrix per-thread base offsets
    const uint32_t aBase = sm + OF_A + (uint32_t)(m0 + (lane & 15)) * RSTRIDE + (lane >> 4) * 16;
    const uint32_t bBase = sm + OF_B + (uint32_t)(lane & 7) * RSTRIDE + ((lane >> 3) & 1) * 16;

    for (int t = blockIdx.x; t < ntiles; t += gridDim.x) {
        const int rowbase = t * TILE;

        // ---- A fill: load X tile, per-row sumsq, bf16 hi/lo split ----
        #pragma unroll
        for (int i = 0; i < 16; i++) {
            int r = m0 + (i << 1) + sub;
            float4 v = X[(size_t)(rowbase + r) * 16 + l16];
            float ss = v.x * v.x + v.y * v.y + v.z * v.z + v.w * v.w;
            ss += __shfl_xor_sync(0xffffffffu, ss, 1);
            ss += __shfl_xor_sync(0xffffffffu, ss, 2);
            ss += __shfl_xor_sync(0xffffffffu, ss, 4);
            ss += __shfl_xor_sync(0xffffffffu, ss, 8);
            if (l16 == 0) sINV[r] = 1.f / fmaxf(ss, 1e-24f);

            __nv_bfloat162 h01 = __floats2bfloat162_rn(v.x, v.y);
            __nv_bfloat162 h23 = __floats2bfloat162_rn(v.z, v.w);
            float2 f01 = __bfloat1622float2(h01);
            float2 f23 = __bfloat1622float2(h23);
            uint2 hi = make_uint2(*reinterpret_cast<uint32_t*>(&h01),
                                  *reinterpret_cast<uint32_t*>(&h23));
            uint2 lo = make_uint2(pack_bf16(v.x - f01.x, v.y - f01.y),
                                  pack_bf16(v.z - f23.x, v.w - f23.y));

            char* rp = smc + OF_A + r * RSTRIDE + l16 * 8;
            *reinterpret_cast<uint2*>(rp)       = hi;   // k [0,64):   xhi
            *reinterpret_cast<uint2*>(rp + 128) = lo;   // k [64,128): xlo
            *reinterpret_cast<uint2*>(rp + 256) = hi;   // k [128,192): xhi
        }
        __syncthreads();

        // ---- GEMM + fused epilogue ----
        float acc[2][2][4];
        #pragma unroll
        for (int a = 0; a < 2; a++)
            #pragma unroll
            for (int h = 0; h < 2; h++)
                #pragma unroll
                for (int c = 0; c < 4; c++) acc[a][h][c] = 0.f;

        #pragma unroll
        for (int nc = 0; nc < 2; nc++) {
            float c[2][8][4];
            #pragma unroll
            for (int a = 0; a < 2; a++)
                #pragma unroll
                for (int n = 0; n < 8; n++)
                    #pragma unroll
                    for (int q = 0; q < 4; q++) c[a][n][q] = 0.f;

            #pragma unroll
            for (int k = 0; k < 12; k++) {
                const uint32_t kb = k * 32;  // k*16 halves * 2B
                uint32_t b[8][2];
                #pragma unroll
                for (int n8 = 0; n8 < 8; n8++)
                    ldsm_x2(b[n8], bBase + (uint32_t)(nc * 64 + n8 * 8) * RSTRIDE + kb);
                #pragma unroll
                for (int m16 = 0; m16 < 2; m16++) {
                    uint32_t a[4];
                    ldsm_x4(a, aBase + (uint32_t)(m16 * 16) * RSTRIDE + kb);
                    #pragma unroll
                    for (int n8 = 0; n8 < 8; n8++)
                        mma16816(c[m16][n8], a, b[n8]);
                }
            }

            // epilogue: p = re^2 + im^2, dot with Mt columns
            #pragma unroll
            for (int m16 = 0; m16 < 2; m16++)
                #pragma unroll
                for (int n8 = 0; n8 < 8; n8++) {
                    int j = nc * 32 + n8 * 4 + (lane & 3);
                    float4 mt = sMt[j];
                    float p0 = c[m16][n8][0] * c[m16][n8][0] + c[m16][n8][1] * c[m16][n8][1];
                    float p1 = c[m16][n8][2] * c[m16][n8][2] + c[m16][n8][3] * c[m16][n8][3];
                    acc[m16][0][0] += mt.x * p0; acc[m16][0][1] += mt.y * p0;
                    acc[m16][0][2] += mt.z * p0; acc[m16][0][3] += mt.w * p0;
                    acc[m16][1][0] += mt.x * p1; acc[m16][1][1] += mt.y * p1;
                    acc[m16][1][2] += mt.z * p1; acc[m16][1][3] += mt.w * p1;
                }
        }

        // ---- reduce over the 4 lanes sharing a row, scale, store ----
        #pragma unroll
        for (int a = 0; a < 2; a++)
            #pragma unroll
            for (int h = 0; h < 2; h++)
                #pragma unroll
                for (int q = 0; q < 4; q++) {
                    float v = acc[a][h][q];
                    v += __shfl_xor_sync(0xffffffffu, v, 1);
                    v += __shfl_xor_sync(0xffffffffu, v, 2);
                    acc[a][h][q] = v;
                }

        if ((lane & 3) == 0) {
            #pragma unroll
            for (int m16 = 0; m16 < 2; m16++)
                #pragma unroll
                for (int h = 0; h < 2; h++) {
                    int r = m0 + m16 * 16 + h * 8 + (lane >> 2);
                    float inv = sINV[r];
                    float4 o;
                    o.x = acc[m16][h][0] * inv + fcb.x;
                    o.y = acc[m16][h][1] * inv + fcb.y;
                    o.z = acc[m16][h][2] * inv + fcb.z;
                    o.w = acc[m16][h][3] * inv + fcb.w;
                    out[rowbase + r] = o;
                }
        }
        __syncthreads();   // protect A/sINV before next tile's fill
    }
}

// ============================================================================
// Launch
// ============================================================================
extern "C" void kernel_launch(void* const* d_in, const int* in_sizes, int n_in,
                              void* d_out, int out_size) {
    const float* x    = (const float*)d_in[0];
    const float* wts  = (const float*)d_in[1];
    const float* fc_w = (const float*)d_in[2];
    const float* fc_b = (const float*)d_in[3];

    int n_items = in_sizes[0] / DIM;   // 262144
    int ntiles  = n_items / TILE;      // 2048

    cudaFuncSetAttribute(qnn_main, cudaFuncAttributeMaxDynamicSharedMemorySize, SMEM_BYTES);

    qnn_build<<<DIM, 32>>>(wts, fc_w, fc_b);
    qnn_main<<<GRIDB, 128, SMEM_BYTES>>>((const float4*)x, (float4*)d_out, ntiles);
}

// round 5
// speedup vs baseline: 1.5015x; 1.5015x over previous
#include <cuda_runtime.h>
#include <cuda_bf16.h>
#include <cstdint>

// ============================================================================
// Problem constants
// ============================================================================
#define NQ     6
#define DIM    64
#define NL     8
#define TILE   128           // batch rows per tile (4 M-groups x 32 rows)
#define GRIDB  296           // persistent CTAs (148 SMs x 2)

// Circuit constants built per-launch by qnn_build.
// W row 2a = Re(U[a][:]), row 2a+1 = Im(U[a][:])  (hi/lo bf16 split), 64 cols.
__device__ __align__(16) __nv_bfloat16 g_Whi[128 * 64];
__device__ __align__(16) __nv_bfloat16 g_Wlo[128 * 64];
__device__ __align__(16) float4 g_Mt[64];   // Mt[a] = {M[0][a],..,M[3][a]}, M = fc_w * Zsign^T
__device__ __align__(16) float4 g_fcb;

// ============================================================================
// PTX helpers (plain sm_103-legal)
// ============================================================================
__device__ __forceinline__ uint32_t smem_u32(const void* p) {
    uint32_t a;
    asm("{ .reg .u64 t; cvta.to.shared.u64 t, %1; cvt.u32.u64 %0, t; }" : "=r"(a) : "l"(p));
    return a;
}
__device__ __forceinline__ void ldsm_x4(uint32_t* r, uint32_t addr) {
    asm volatile("ldmatrix.sync.aligned.m8n8.x4.shared.b16 {%0,%1,%2,%3}, [%4];"
                 : "=r"(r[0]), "=r"(r[1]), "=r"(r[2]), "=r"(r[3]) : "r"(addr));
}
__device__ __forceinline__ void mma16816(float* c, const uint32_t* a, const uint32_t* b) {
    asm volatile("mma.sync.aligned.m16n8k16.row.col.f32.bf16.bf16.f32 "
                 "{%0,%1,%2,%3}, {%4,%5,%6,%7}, {%8,%9}, {%0,%1,%2,%3};"
                 : "+f"(c[0]), "+f"(c[1]), "+f"(c[2]), "+f"(c[3])
                 : "r"(a[0]), "r"(a[1]), "r"(a[2]), "r"(a[3]), "r"(b[0]), "r"(b[1]));
}
__device__ __forceinline__ void barx(int id) {
    asm volatile("bar.sync %0, %1;" :: "r"(id), "r"(64) : "memory");
}
__device__ __forceinline__ uint32_t pack_bf16(float x, float y) {
    __nv_bfloat162 h = __floats2bfloat162_rn(x, y);
    return *reinterpret_cast<uint32_t*>(&h);
}

// ============================================================================
// Kernel A: build U columns (one warp per basis column), emit Whi/Wlo/Mt/fcb.
// Each lane holds 2 complex amplitudes: amp = lane + 32*slot.
// qubit q acts on amplitude-index bit b = 5-q (qubit 0 = MSB).
// ============================================================================
__global__ void qnn_build(const float* __restrict__ weights,
                          const float* __restrict__ fc_w,
                          const float* __restrict__ fc_b) {
    const int w = blockIdx.x;
    const int lane = threadIdx.x;

    float sr0 = (lane == w) ? 1.f : 0.f,      si0 = 0.f;
    float sr1 = (lane + 32 == w) ? 1.f : 0.f, si1 = 0.f;

    for (int l = 0; l < NL; l++) {
        for (int q = 0; q < NQ; q++) {
            const float* g = weights + (l * NQ + q) * 3;
            float phi = g[0], th = g[1], om = g[2];
            float st, ct; sincosf(0.5f * th, &st, &ct);
            float sa, ca; sincosf(0.5f * (phi + om), &sa, &ca);
            float sb, cb; sincosf(0.5f * (phi - om), &sb, &cb);
            float m00r =  ca * ct, m00i = -sa * ct;
            float m01r = -cb * st, m01i = -sb * st;
            float m10r =  cb * st, m10i = -sb * st;
            float m11r =  ca * ct, m11i =  sa * ct;
            int b = 5 - q;
            if (b == 5) {
                float nr0 = m00r*sr0 - m00i*si0 + m01r*sr1 - m01i*si1;
                float ni0 = m00r*si0 + m00i*sr0 + m01r*si1 + m01i*sr1;
                float nr1 = m10r*sr0 - m10i*si0 + m11r*sr1 - m11i*si1;
                float ni1 = m10r*si0 + m10i*sr0 + m11r*si1 + m11i*sr1;
                sr0 = nr0; si0 = ni0; sr1 = nr1; si1 = ni1;
            } else {
                int msk = 1 << b;
                int bit = (lane >> b) & 1;
                float dr = bit ? m11r : m00r, di = bit ? m11i : m00i;
                float orr = bit ? m10r : m01r, oi = bit ? m10i : m01i;
                float pr, pi, nr, ni;
                pr = __shfl_xor_sync(0xffffffffu, sr0, msk);
                pi = __shfl_xor_sync(0xffffffffu, si0, msk);
                nr = dr*sr0 - di*si0 + orr*pr - oi*pi;
                ni = dr*si0 + di*sr0 + orr*pi + oi*pr;
                sr0 = nr; si0 = ni;
                pr = __shfl_xor_sync(0xffffffffu, sr1, msk);
                pi = __shfl_xor_sync(0xffffffffu, si1, msk);
                nr = dr*sr1 - di*si1 + orr*pr - oi*pi;
                ni = dr*si1 + di*sr1 + orr*pi + oi*pr;
                sr1 = nr; si1 = ni;
            }
        }
        int r = (l % (NQ - 1)) + 1;
        for (int q = 0; q < NQ; q++) {
            int t = (q + r) % NQ;
            int bc = 5 - q, bt = 5 - t;
            if (bc == 5) {
                int m = 1 << bt;
                sr1 = __shfl_xor_sync(0xffffffffu, sr1, m);
                si1 = __shfl_xor_sync(0xffffffffu, si1, m);
            } else if (bt == 5) {
                if ((lane >> bc) & 1) {
                    float tmp;
                    tmp = sr0; sr0 = sr1; sr1 = tmp;
                    tmp = si0; si0 = si1; si1 = tmp;
                }
            } else {
                int m = 1 << bt;
                int ctrl = (lane >> bc) & 1;
                float pr, pi;
                pr = __shfl_xor_sync(0xffffffffu, sr0, m);
                pi = __shfl_xor_sync(0xffffffffu, si0, m);
                if (ctrl) { sr0 = pr; si0 = pi; }
                pr = __shfl_xor_sync(0xffffffffu, sr1, m);
                pi = __shfl_xor_sync(0xffffffffu, si1, m);
                if (ctrl) { sr1 = pr; si1 = pi; }
            }
        }
    }

    auto store = [&](int row, float v) {
        __nv_bfloat16 h = __float2bfloat16(v);
        float hf = __bfloat162float(h);
        __nv_bfloat16 lo = __float2bfloat16(v - hf);
        g_Whi[row * 64 + w] = h;
        g_Wlo[row * 64 + w] = lo;
    };
    store(2 * lane,            sr0);
    store(2 * lane + 1,        si0);
    store(2 * (lane + 32),     sr1);
    store(2 * (lane + 32) + 1, si1);

    if (w == 0) {
        for (int s = 0; s < 2; s++) {
            int d = lane + 32 * s;
            float m[4];
            for (int c = 0; c < 4; c++) {
                float acc = 0.f;
                for (int i = 0; i < NQ; i++) {
                    int bit = (d >> (5 - i)) & 1;
                    acc += fc_w[c * NQ + i] * (bit ? -1.f : 1.f);
                }
                m[c] = acc;
            }
            g_Mt[d] = make_float4(m[0], m[1], m[2], m[3]);
        }
        if (lane == 0)
            g_fcb = make_float4(fc_b[0], fc_b[1], fc_b[2], fc_b[3]);
    }
}

// ============================================================================
// Kernel B: persistent, 256 thr = 8 warps = 4 M-groups(32 rows) x 2 N-halves(64).
// A direct from global into mma fragments (per-kc, low reg pressure);
// B in smem via ldmatrix x4 (Bhi frags reused for hi*hi and lo*hi terms);
// no __syncthreads in tile loop — only per-pair named barriers.
// ============================================================================
#define STRIDE_B 272                          // 256B data + 16B pad, conflict-free
#define OF_MT   0                             // 64 float4 = 1 KB
#define OF_XB   1024                          // xbuf: 2 parity x 4 pairs x 32 rows x 16B = 4 KB
#define OF_B    5120
#define SMEM_BYTES (OF_B + 128 * STRIDE_B)    // 5120 + 34816 = 39936

__global__ void __launch_bounds__(256, 2)
qnn_main(const float2* __restrict__ X, float4* __restrict__ out, int ntiles) {
    extern __shared__ char smc[];
    const uint32_t sm = smem_u32(smc);
    const int tid = threadIdx.x, wid = tid >> 5, lane = tid & 31;

    // ---- one-time staging: B rows = [Whi(64 h) | Wlo(64 h)], stride 272B ----
    for (int idx = tid; idx < 128 * 64; idx += 256) {
        int wrow = idx >> 6, u = idx & 63;
        int k = u * 2;
        uint32_t val = (k < 64)
            ? reinterpret_cast<const uint32_t*>(g_Whi)[wrow * 32 + (k >> 1)]
            : reinterpret_cast<const uint32_t*>(g_Wlo)[wrow * 32 + ((k - 64) >> 1)];
        *reinterpret_cast<uint32_t*>(smc + OF_B + wrow * STRIDE_B + k * 2) = val;
    }
    if (tid < 64) reinterpret_cast<float4*>(smc + OF_MT)[tid] = g_Mt[tid];
    const float4 fcb = g_fcb;
    __syncthreads();

    const int w3    = wid & 3;        // M group: rows w3*32 .. +31
    const int nhalf = wid >> 2;       // N half (0: cols 0-63, 1: cols 64-127)
    const int m0    = w3 * 32;
    const int nbase = nhalf * 64;
    const int r0    = m0 + (lane >> 2);   // rows covered: r0 + {0,8,16,24}
    const int l4    = lane & 3;

    // ldmatrix x4 base: b[0]={n0-7,k0-7} b[1]={n0-7,k8-15} b[2]={n8-15,k0-7} b[3]={n8-15,k8-15}
    const uint32_t bB = sm + OF_B
        + (uint32_t)(nbase + ((lane >> 4) & 1) * 8 + (lane & 7)) * STRIDE_B
        + ((lane >> 3) & 1) * 16;

    float4* xb = reinterpret_cast<float4*>(smc + OF_XB);
    const float4* sMt = reinterpret_cast<const float4*>(smc + OF_MT);

    int par = 0;
    for (int t = blockIdx.x; t < ntiles; t += gridDim.x) {
        const int rowbase = t * TILE;

        float c[2][8][4];            // [m16 block][n8 group][quad]
        #pragma unroll
        for (int m = 0; m < 2; m++)
            #pragma unroll
            for (int j = 0; j < 8; j++)
                #pragma unroll
                for (int q = 0; q < 4; q++) c[m][j][q] = 0.f;
        float ss[4] = {0.f, 0.f, 0.f, 0.f};   // per row-group (r0 + 8g) sumsq

        #pragma unroll
        for (int kc = 0; kc < 4; kc++) {
            // ---- A fragments for this k-chunk: 2 m16 blocks, hi + lo split ----
            uint32_t ah[2][4], al[2][4];
            #pragma unroll
            for (int m = 0; m < 2; m++) {
                #pragma unroll
                for (int h = 0; h < 2; h++) {
                    const int fi = l4 + 4 * h + 8 * kc;   // float2 index within row
                    const int rA = r0 + m * 16;
                    float2 v0 = X[(size_t)(rowbase + rA) * 32 + fi];
                    float2 v1 = X[(size_t)(rowbase + rA + 8) * 32 + fi];
                    ss[2 * m]     += v0.x * v0.x + v0.y * v0.y;
                    ss[2 * m + 1] += v1.x * v1.x + v1.y * v1.y;
                    __nv_bfloat162 h0 = __floats2bfloat162_rn(v0.x, v0.y);
                    __nv_bfloat162 h1 = __floats2bfloat162_rn(v1.x, v1.y);
                    float2 f0 = __bfloat1622float2(h0);
                    float2 f1 = __bfloat1622float2(h1);
                    ah[m][h * 2 + 0] = *reinterpret_cast<uint32_t*>(&h0);
                    ah[m][h * 2 + 1] = *reinterpret_cast<uint32_t*>(&h1);
                    al[m][h * 2 + 0] = pack_bf16(v0.x - f0.x, v0.y - f0.y);
                    al[m][h * 2 + 1] = pack_bf16(v1.x - f1.x, v1.y - f1.y);
                }
            }
            // ---- Bhi: used by both ah and al terms ----
            #pragma unroll
            for (int pr = 0; pr < 4; pr++) {
                uint32_t b[4];
                ldsm_x4(b, bB + (uint32_t)(pr * 16) * STRIDE_B + kc * 32);
                #pragma unroll
                for (int m = 0; m < 2; m++) {
                    mma16816(c[m][pr * 2],     ah[m], b);
                    mma16816(c[m][pr * 2 + 1], ah[m], b + 2);
                    mma16816(c[m][pr * 2],     al[m], b);
                    mma16816(c[m][pr * 2 + 1], al[m], b + 2);
                }
            }
            // ---- Blo x Ahi ----
            #pragma unroll
            for (int pr = 0; pr < 4; pr++) {
                uint32_t b[4];
                ldsm_x4(b, bB + (uint32_t)(pr * 16) * STRIDE_B + 128 + kc * 32);
                #pragma unroll
                for (int m = 0; m < 2; m++) {
                    mma16816(c[m][pr * 2],     ah[m], b);
                    mma16816(c[m][pr * 2 + 1], ah[m], b + 2);
                }
            }
        }

        // ---- row norms ----
        #pragma unroll
        for (int g = 0; g < 4; g++) {
            ss[g] += __shfl_xor_sync(0xffffffffu, ss[g], 1);
            ss[g] += __shfl_xor_sync(0xffffffffu, ss[g], 2);
        }

        // ---- epilogue: p = re^2 + im^2 ; partial 4-class dot against Mt ----
        float acc[4][4];   // [row-group g = 2m+h][class]
        #pragma unroll
        for (int g = 0; g < 4; g++)
            #pragma unroll
            for (int q = 0; q < 4; q++) acc[g][q] = 0.f;

        #pragma unroll
        for (int m = 0; m < 2; m++)
            #pragma unroll
            for (int j = 0; j < 8; j++) {
                const int amp = (nbase >> 1) + j * 4 + l4;
                float4 mt = sMt[amp];
                float p0 = c[m][j][0] * c[m][j][0] + c[m][j][1] * c[m][j][1];
                float p1 = c[m][j][2] * c[m][j][2] + c[m][j][3] * c[m][j][3];
                acc[2*m][0] += mt.x * p0; acc[2*m][1] += mt.y * p0;
                acc[2*m][2] += mt.z * p0; acc[2*m][3] += mt.w * p0;
                acc[2*m+1][0] += mt.x * p1; acc[2*m+1][1] += mt.y * p1;
                acc[2*m+1][2] += mt.z * p1; acc[2*m+1][3] += mt.w * p1;
            }
        #pragma unroll
        for (int g = 0; g < 4; g++)
            #pragma unroll
            for (int q = 0; q < 4; q++) {
                acc[g][q] += __shfl_xor_sync(0xffffffffu, acc[g][q], 1);
                acc[g][q] += __shfl_xor_sync(0xffffffffu, acc[g][q], 2);
            }

        // ---- pair exchange (nhalf 1 -> nhalf 0), scale, store ----
        float4* xbp = xb + par * 128 + w3 * 32;     // 32 rows x float4 per pair
        if (nhalf == 1) {
            if (l4 == 0) {
                #pragma unroll
                for (int g = 0; g < 4; g++) {
                    int rloc = (g >> 1) * 16 + (g & 1) * 8 + (lane >> 2);
                    xbp[rloc] = make_float4(acc[g][0], acc[g][1], acc[g][2], acc[g][3]);
                }
            }
            barx(1 + w3);
        } else {
            barx(1 + w3);
            if (l4 == 0) {
                #pragma unroll
                for (int g = 0; g < 4; g++) {
                    int rloc = (g >> 1) * 16 + (g & 1) * 8 + (lane >> 2);
                    float4 o = xbp[rloc];
                    float inv = 1.f / fmaxf(ss[g], 1e-24f);
                    float4 r;
                    r.x = (acc[g][0] + o.x) * inv + fcb.x;
                    r.y = (acc[g][1] + o.y) * inv + fcb.y;
                    r.z = (acc[g][2] + o.z) * inv + fcb.z;
                    r.w = (acc[g][3] + o.w) * inv + fcb.w;
                    out[rowbase + m0 + rloc] = r;
                }
            }
        }
        par ^= 1;
    }
}

// ============================================================================
// Launch
// ============================================================================
extern "C" void kernel_launch(void* const* d_in, const int* in_sizes, int n_in,
                              void* d_out, int out_size) {
    const float* x    = (const float*)d_in[0];
    const float* wts  = (const float*)d_in[1];
    const float* fc_w = (const float*)d_in[2];
    const float* fc_b = (const float*)d_in[3];

    int n_items = in_sizes[0] / DIM;   // 262144
    int ntiles  = n_items / TILE;      // 2048

    qnn_build<<<DIM, 32>>>(wts, fc_w, fc_b);
    qnn_main<<<GRIDB, 256, SMEM_BYTES>>>((const float2*)x, (float4*)d_out, ntiles);
}

// round 6
// speedup vs baseline: 1.6730x; 1.1142x over previous
#include <cuda_runtime.h>
#include <cuda_fp16.h>
#include <cstdint>

// ============================================================================
// Problem constants
// ============================================================================
#define NQ     6
#define DIM    64
#define NL     8
#define TILE   128           // batch rows per tile (4 M-groups x 32 rows)
#define GRIDB  296           // persistent CTAs (148 SMs x 2)

// Circuit constants built per-launch by qnn_build.
// W row 2a = Re(U[a][:]), row 2a+1 = Im(U[a][:]), fp16, 64 cols.
__device__ __align__(16) __half g_Wh[128 * 64];
__device__ __align__(16) float4 g_Mt[64];   // Mt[a] = {M[0][a],..,M[3][a]}, M = fc_w * Zsign^T
__device__ __align__(16) float4 g_fcb;

// ============================================================================
// PTX helpers (plain sm_103-legal)
// ============================================================================
__device__ __forceinline__ uint32_t smem_u32(const void* p) {
    uint32_t a;
    asm("{ .reg .u64 t; cvta.to.shared.u64 t, %1; cvt.u32.u64 %0, t; }" : "=r"(a) : "l"(p));
    return a;
}
__device__ __forceinline__ void ldsm_x4(uint32_t* r, uint32_t addr) {
    asm volatile("ldmatrix.sync.aligned.m8n8.x4.shared.b16 {%0,%1,%2,%3}, [%4];"
                 : "=r"(r[0]), "=r"(r[1]), "=r"(r[2]), "=r"(r[3]) : "r"(addr));
}
__device__ __forceinline__ void mma16816(float* c, const uint32_t* a, const uint32_t* b) {
    asm volatile("mma.sync.aligned.m16n8k16.row.col.f32.f16.f16.f32 "
                 "{%0,%1,%2,%3}, {%4,%5,%6,%7}, {%8,%9}, {%0,%1,%2,%3};"
                 : "+f"(c[0]), "+f"(c[1]), "+f"(c[2]), "+f"(c[3])
                 : "r"(a[0]), "r"(a[1]), "r"(a[2]), "r"(a[3]), "r"(b[0]), "r"(b[1]));
}
__device__ __forceinline__ void barx(int id) {
    asm volatile("bar.sync %0, %1;" :: "r"(id), "r"(64) : "memory");
}

// ============================================================================
// Kernel A: build U columns (one warp per basis column), emit Wh/Mt/fcb.
// Each lane holds 2 complex amplitudes: amp = lane + 32*slot.
// qubit q acts on amplitude-index bit b = 5-q (qubit 0 = MSB).
// ============================================================================
__global__ void qnn_build(const float* __restrict__ weights,
                          const float* __restrict__ fc_w,
                          const float* __restrict__ fc_b) {
    const int w = blockIdx.x;
    const int lane = threadIdx.x;

    float sr0 = (lane == w) ? 1.f : 0.f,      si0 = 0.f;
    float sr1 = (lane + 32 == w) ? 1.f : 0.f, si1 = 0.f;

    for (int l = 0; l < NL; l++) {
        for (int q = 0; q < NQ; q++) {
            const float* g = weights + (l * NQ + q) * 3;
            float phi = g[0], th = g[1], om = g[2];
            float st, ct; sincosf(0.5f * th, &st, &ct);
            float sa, ca; sincosf(0.5f * (phi + om), &sa, &ca);
            float sb, cb; sincosf(0.5f * (phi - om), &sb, &cb);
            float m00r =  ca * ct, m00i = -sa * ct;
            float m01r = -cb * st, m01i = -sb * st;
            float m10r =  cb * st, m10i = -sb * st;
            float m11r =  ca * ct, m11i =  sa * ct;
            int b = 5 - q;
            if (b == 5) {
                float nr0 = m00r*sr0 - m00i*si0 + m01r*sr1 - m01i*si1;
                float ni0 = m00r*si0 + m00i*sr0 + m01r*si1 + m01i*sr1;
                float nr1 = m10r*sr0 - m10i*si0 + m11r*sr1 - m11i*si1;
                float ni1 = m10r*si0 + m10i*sr0 + m11r*si1 + m11i*sr1;
                sr0 = nr0; si0 = ni0; sr1 = nr1; si1 = ni1;
            } else {
                int msk = 1 << b;
                int bit = (lane >> b) & 1;
                float dr = bit ? m11r : m00r, di = bit ? m11i : m00i;
                float orr = bit ? m10r : m01r, oi = bit ? m10i : m01i;
                float pr, pi, nr, ni;
                pr = __shfl_xor_sync(0xffffffffu, sr0, msk);
                pi = __shfl_xor_sync(0xffffffffu, si0, msk);
                nr = dr*sr0 - di*si0 + orr*pr - oi*pi;
                ni = dr*si0 + di*sr0 + orr*pi + oi*pr;
                sr0 = nr; si0 = ni;
                pr = __shfl_xor_sync(0xffffffffu, sr1, msk);
                pi = __shfl_xor_sync(0xffffffffu, si1, msk);
                nr = dr*sr1 - di*si1 + orr*pr - oi*pi;
                ni = dr*si1 + di*sr1 + orr*pi + oi*pr;
                sr1 = nr; si1 = ni;
            }
        }
        int r = (l % (NQ - 1)) + 1;
        for (int q = 0; q < NQ; q++) {
            int t = (q + r) % NQ;
            int bc = 5 - q, bt = 5 - t;
            if (bc == 5) {
                int m = 1 << bt;
                sr1 = __shfl_xor_sync(0xffffffffu, sr1, m);
                si1 = __shfl_xor_sync(0xffffffffu, si1, m);
            } else if (bt == 5) {
                if ((lane >> bc) & 1) {
                    float tmp;
                    tmp = sr0; sr0 = sr1; sr1 = tmp;
                    tmp = si0; si0 = si1; si1 = tmp;
                }
            } else {
                int m = 1 << bt;
                int ctrl = (lane >> bc) & 1;
                float pr, pi;
                pr = __shfl_xor_sync(0xffffffffu, sr0, m);
                pi = __shfl_xor_sync(0xffffffffu, si0, m);
                if (ctrl) { sr0 = pr; si0 = pi; }
                pr = __shfl_xor_sync(0xffffffffu, sr1, m);
                pi = __shfl_xor_sync(0xffffffffu, si1, m);
                if (ctrl) { sr1 = pr; si1 = pi; }
            }
        }
    }

    g_Wh[(2 * lane)            * 64 + w] = __float2half(sr0);
    g_Wh[(2 * lane + 1)        * 64 + w] = __float2half(si0);
    g_Wh[(2 * (lane + 32))     * 64 + w] = __float2half(sr1);
    g_Wh[(2 * (lane + 32) + 1) * 64 + w] = __float2half(si1);

    if (w == 0) {
        for (int s = 0; s < 2; s++) {
            int d = lane + 32 * s;
            float m[4];
            for (int c = 0; c < 4; c++) {
                float acc = 0.f;
                for (int i = 0; i < NQ; i++) {
                    int bit = (d >> (5 - i)) & 1;
                    acc += fc_w[c * NQ + i] * (bit ? -1.f : 1.f);
                }
                m[c] = acc;
            }
            g_Mt[d] = make_float4(m[0], m[1], m[2], m[3]);
        }
        if (lane == 0)
            g_fcb = make_float4(fc_b[0], fc_b[1], fc_b[2], fc_b[3]);
    }
}

// ============================================================================
// Kernel B: persistent, 256 thr = 8 warps = 4 M-groups(32 rows) x 2 N-halves(64).
// fp16 x-exact 2-block: y = (xh + xl) * wh.  A direct from global into mma
// fragments; B (wh only, K=64) in smem via ldmatrix x4, each B frag feeds
// both the xh and xl MMAs.  No __syncthreads in tile loop.
// ============================================================================
#define STRIDE_B 144                          // 128B data + 16B pad, conflict-free
#define OF_MT   0                             // 64 float4 = 1 KB
#define OF_XB   1024                          // xbuf: 2 parity x 4 pairs x 32 rows x 16B = 4 KB
#define OF_B    5120
#define SMEM_BYTES (OF_B + 128 * STRIDE_B)    // 5120 + 18432 = 23552

__global__ void __launch_bounds__(256, 2)
qnn_main(const float2* __restrict__ X, float4* __restrict__ out, int ntiles) {
    extern __shared__ char smc[];
    const uint32_t sm = smem_u32(smc);
    const int tid = threadIdx.x, wid = tid >> 5, lane = tid & 31;

    // ---- one-time staging: B rows = wh (64 halves = 128B), stride 144B ----
    for (int idx = tid; idx < 128 * 32; idx += 256) {
        int wrow = idx >> 5, u = idx & 31;    // u32 unit (2 halves)
        uint32_t val = reinterpret_cast<const uint32_t*>(g_Wh)[wrow * 32 + u];
        *reinterpret_cast<uint32_t*>(smc + OF_B + wrow * STRIDE_B + u * 4) = val;
    }
    if (tid < 64) reinterpret_cast<float4*>(smc + OF_MT)[tid] = g_Mt[tid];
    const float4 fcb = g_fcb;
    __syncthreads();

    const int w3    = wid & 3;        // M group: rows w3*32 .. +31
    const int nhalf = wid >> 2;       // N half (0: cols 0-63, 1: cols 64-127)
    const int m0    = w3 * 32;
    const int nbase = nhalf * 64;
    const int r0    = m0 + (lane >> 2);   // rows covered: r0 + {0,8,16,24}
    const int l4    = lane & 3;

    // ldmatrix x4 base: b[0]={n0-7,k0-7} b[1]={n0-7,k8-15} b[2]={n8-15,k0-7} b[3]={n8-15,k8-15}
    const uint32_t bB = sm + OF_B
        + (uint32_t)(nbase + ((lane >> 4) & 1) * 8 + (lane & 7)) * STRIDE_B
        + ((lane >> 3) & 1) * 16;

    float4* xb = reinterpret_cast<float4*>(smc + OF_XB);
    const float4* sMt = reinterpret_cast<const float4*>(smc + OF_MT);

    int par = 0;
    for (int t = blockIdx.x; t < ntiles; t += gridDim.x) {
        const int rowbase = t * TILE;

        float c[2][8][4];            // [m16 block][n8 group][quad]
        #pragma unroll
        for (int m = 0; m < 2; m++)
            #pragma unroll
            for (int j = 0; j < 8; j++)
                #pragma unroll
                for (int q = 0; q < 4; q++) c[m][j][q] = 0.f;
        float ss[4] = {0.f, 0.f, 0.f, 0.f};   // per row-group (r0 + 8g) sumsq

        #pragma unroll
        for (int kc = 0; kc < 4; kc++) {
            // ---- A fragments for this k-chunk: 2 m16 blocks, fp16 hi + residual ----
            uint32_t ah[2][4], al[2][4];
            #pragma unroll
            for (int m = 0; m < 2; m++) {
                #pragma unroll
                for (int h = 0; h < 2; h++) {
                    const int fi = l4 + 4 * h + 8 * kc;   // float2 index within row
                    const int rA = r0 + m * 16;
                    float2 v0 = X[(size_t)(rowbase + rA) * 32 + fi];
                    float2 v1 = X[(size_t)(rowbase + rA + 8) * 32 + fi];
                    ss[2 * m]     += v0.x * v0.x + v0.y * v0.y;
                    ss[2 * m + 1] += v1.x * v1.x + v1.y * v1.y;
                    __half2 h0 = __floats2half2_rn(v0.x, v0.y);
                    __half2 h1 = __floats2half2_rn(v1.x, v1.y);
                    float2 f0 = __half22float2(h0);
                    float2 f1 = __half22float2(h1);
                    __half2 l0 = __floats2half2_rn(v0.x - f0.x, v0.y - f0.y);
                    __half2 l1 = __floats2half2_rn(v1.x - f1.x, v1.y - f1.y);
                    ah[m][h * 2 + 0] = *reinterpret_cast<uint32_t*>(&h0);
                    ah[m][h * 2 + 1] = *reinterpret_cast<uint32_t*>(&h1);
                    al[m][h * 2 + 0] = *reinterpret_cast<uint32_t*>(&l0);
                    al[m][h * 2 + 1] = *reinterpret_cast<uint32_t*>(&l1);
                }
            }
            // ---- B frag per n16 group; feeds both xh and xl MMAs ----
            #pragma unroll
            for (int pr = 0; pr < 4; pr++) {
                uint32_t b[4];
                ldsm_x4(b, bB + (uint32_t)(pr * 16) * STRIDE_B + kc * 32);
                #pragma unroll
                for (int m = 0; m < 2; m++) {
                    mma16816(c[m][pr * 2],     ah[m], b);
                    mma16816(c[m][pr * 2 + 1], ah[m], b + 2);
                    mma16816(c[m][pr * 2],     al[m], b);
                    mma16816(c[m][pr * 2 + 1], al[m], b + 2);
                }
            }
        }

        // ---- row norms ----
        #pragma unroll
        for (int g = 0; g < 4; g++) {
            ss[g] += __shfl_xor_sync(0xffffffffu, ss[g], 1);
            ss[g] += __shfl_xor_sync(0xffffffffu, ss[g], 2);
        }

        // ---- epilogue: p = re^2 + im^2 ; partial 4-class dot against Mt ----
        float acc[4][4];   // [row-group g = 2m+h][class]
        #pragma unroll
        for (int g = 0; g < 4; g++)
            #pragma unroll
            for (int q = 0; q < 4; q++) acc[g][q] = 0.f;

        #pragma unroll
        for (int m = 0; m < 2; m++)
            #pragma unroll
            for (int j = 0; j < 8; j++) {
                const int amp = (nbase >> 1) + j * 4 + l4;
                float4 mt = sMt[amp];
                float p0 = c[m][j][0] * c[m][j][0] + c[m][j][1] * c[m][j][1];
                float p1 = c[m][j][2] * c[m][j][2] + c[m][j][3] * c[m][j][3];
                acc[2*m][0] += mt.x * p0; acc[2*m][1] += mt.y * p0;
                acc[2*m][2] += mt.z * p0; acc[2*m][3] += mt.w * p0;
                acc[2*m+1][0] += mt.x * p1; acc[2*m+1][1] += mt.y * p1;
                acc[2*m+1][2] += mt.z * p1; acc[2*m+1][3] += mt.w * p1;
            }
        #pragma unroll
        for (int g = 0; g < 4; g++)
            #pragma unroll
            for (int q = 0; q < 4; q++) {
                acc[g][q] += __shfl_xor_sync(0xffffffffu, acc[g][q], 1);
                acc[g][q] += __shfl_xor_sync(0xffffffffu, acc[g][q], 2);
            }

        // ---- pair exchange (nhalf 1 -> nhalf 0), scale, store ----
        float4* xbp = xb + par * 128 + w3 * 32;     // 32 rows x float4 per pair
        if (nhalf == 1) {
            if (l4 == 0) {
                #pragma unroll
                for (int g = 0; g < 4; g++) {
                    int rloc = (g >> 1) * 16 + (g & 1) * 8 + (lane >> 2);
                    xbp[rloc] = make_float4(acc[g][0], acc[g][1], acc[g][2], acc[g][3]);
                }
            }
            barx(1 + w3);
        } else {
            barx(1 + w3);
            if (l4 == 0) {
                #pragma unroll
                for (int g = 0; g < 4; g++) {
                    int rloc = (g >> 1) * 16 + (g & 1) * 8 + (lane >> 2);
                    float4 o = xbp[rloc];
                    float inv = 1.f / fmaxf(ss[g], 1e-24f);
                    float4 r;
                    r.x = (acc[g][0] + o.x) * inv + fcb.x;
                    r.y = (acc[g][1] + o.y) * inv + fcb.y;
                    r.z = (acc[g][2] + o.z) * inv + fcb.z;
                    r.w = (acc[g][3] + o.w) * inv + fcb.w;
                    out[rowbase + m0 + rloc] = r;
                }
            }
        }
        par ^= 1;
    }
}

// ============================================================================
// Launch
// ============================================================================
extern "C" void kernel_launch(void* const* d_in, const int* in_sizes, int n_in,
                              void* d_out, int out_size) {
    const float* x    = (const float*)d_in[0];
    const float* wts  = (const float*)d_in[1];
    const float* fc_w = (const float*)d_in[2];
    const float* fc_b = (const float*)d_in[3];

    int n_items = in_sizes[0] / DIM;   // 262144
    int ntiles  = n_items / TILE;      // 2048

    qnn_build<<<DIM, 32>>>(wts, fc_w, fc_b);
    qnn_main<<<GRIDB, 256, SMEM_BYTES>>>((const float2*)x, (float4*)d_out, ntiles);
}

// round 8
// speedup vs baseline: 1.8789x; 1.1231x over previous
#include <cuda_runtime.h>
#include <cuda_fp16.h>
#include <cstdint>

// ============================================================================
// Problem constants
// ============================================================================
#define NQ     6
#define DIM    64
#define NL     8
#define TILE   128           // batch rows per tile (8 warps x 16 rows)
#define GRIDB  296           // persistent CTAs (148 SMs x 2)

// Circuit constants built per-launch by qnn_build.
// W row 2a = Re(U[a][:]), row 2a+1 = Im(U[a][:]), fp16, 64 cols.
__device__ __align__(16) __half g_Wh[128 * 64];
__device__ __align__(16) float4 g_Mt[64];   // Mt[a] = {M[0][a],..,M[3][a]}, M = fc_w * Zsign^T
__device__ __align__(16) float4 g_fcb;

// ============================================================================
// PTX helpers (plain sm_103-legal)
// ============================================================================
__device__ __forceinline__ uint32_t smem_u32(const void* p) {
    uint32_t a;
    asm("{ .reg .u64 t; cvta.to.shared.u64 t, %1; cvt.u32.u64 %0, t; }" : "=r"(a) : "l"(p));
    return a;
}
__device__ __forceinline__ void ldsm_x4(uint32_t* r, uint32_t addr) {
    asm volatile("ldmatrix.sync.aligned.m8n8.x4.shared.b16 {%0,%1,%2,%3}, [%4];"
                 : "=r"(r[0]), "=r"(r[1]), "=r"(r[2]), "=r"(r[3]) : "r"(addr));
}
__device__ __forceinline__ void mma16816(float* c, const uint32_t* a, const uint32_t* b) {
    asm volatile("mma.sync.aligned.m16n8k16.row.col.f32.f16.f16.f32 "
                 "{%0,%1,%2,%3}, {%4,%5,%6,%7}, {%8,%9}, {%0,%1,%2,%3};"
                 : "+f"(c[0]), "+f"(c[1]), "+f"(c[2]), "+f"(c[3])
                 : "r"(a[0]), "r"(a[1]), "r"(a[2]), "r"(a[3]), "r"(b[0]), "r"(b[1]));
}

// ============================================================================
// Kernel A: build U columns (one warp per basis column), emit Wh/Mt/fcb.
// Each lane holds 2 complex amplitudes: amp = lane + 32*slot.
// qubit q acts on amplitude-index bit b = 5-q (qubit 0 = MSB).
// ============================================================================
__global__ void qnn_build(const float* __restrict__ weights,
                          const float* __restrict__ fc_w,
                          const float* __restrict__ fc_b) {
    const int w = blockIdx.x;
    const int lane = threadIdx.x;

    float sr0 = (lane == w) ? 1.f : 0.f,      si0 = 0.f;
    float sr1 = (lane + 32 == w) ? 1.f : 0.f, si1 = 0.f;

    for (int l = 0; l < NL; l++) {
        for (int q = 0; q < NQ; q++) {
            const float* g = weights + (l * NQ + q) * 3;
            float phi = g[0], th = g[1], om = g[2];
            float st, ct; sincosf(0.5f * th, &st, &ct);
            float sa, ca; sincosf(0.5f * (phi + om), &sa, &ca);
            float sb, cb; sincosf(0.5f * (phi - om), &sb, &cb);
            float m00r =  ca * ct, m00i = -sa * ct;
            float m01r = -cb * st, m01i = -sb * st;
            float m10r =  cb * st, m10i = -sb * st;
            float m11r =  ca * ct, m11i =  sa * ct;
            int b = 5 - q;
            if (b == 5) {
                float nr0 = m00r*sr0 - m00i*si0 + m01r*sr1 - m01i*si1;
                float ni0 = m00r*si0 + m00i*sr0 + m01r*si1 + m01i*sr1;
                float nr1 = m10r*sr0 - m10i*si0 + m11r*sr1 - m11i*si1;
                float ni1 = m10r*si0 + m10i*sr0 + m11r*si1 + m11i*sr1;
                sr0 = nr0; si0 = ni0; sr1 = nr1; si1 = ni1;
            } else {
                int msk = 1 << b;
                int bit = (lane >> b) & 1;
                float dr = bit ? m11r : m00r, di = bit ? m11i : m00i;
                float orr = bit ? m10r : m01r, oi = bit ? m10i : m01i;
                float pr, pi, nr, ni;
                pr = __shfl_xor_sync(0xffffffffu, sr0, msk);
                pi = __shfl_xor_sync(0xffffffffu, si0, msk);
                nr = dr*sr0 - di*si0 + orr*pr - oi*pi;
                ni = dr*si0 + di*sr0 + orr*pi + oi*pr;
                sr0 = nr; si0 = ni;
                pr = __shfl_xor_sync(0xffffffffu, sr1, msk);
                pi = __shfl_xor_sync(0xffffffffu, si1, msk);
                nr = dr*sr1 - di*si1 + orr*pr - oi*pi;
                ni = dr*si1 + di*sr1 + orr*pi + oi*pr;
                sr1 = nr; si1 = ni;
            }
        }
        int r = (l % (NQ - 1)) + 1;
        for (int q = 0; q < NQ; q++) {
            int t = (q + r) % NQ;
            int bc = 5 - q, bt = 5 - t;
            if (bc == 5) {
                int m = 1 << bt;
                sr1 = __shfl_xor_sync(0xffffffffu, sr1, m);
                si1 = __shfl_xor_sync(0xffffffffu, si1, m);
            } else if (bt == 5) {
                if ((lane >> bc) & 1) {
                    float tmp;
                    tmp = sr0; sr0 = sr1; sr1 = tmp;
                    tmp = si0; si0 = si1; si1 = tmp;
                }
            } else {
                int m = 1 << bt;
                int ctrl = (lane >> bc) & 1;
                float pr, pi;
                pr = __shfl_xor_sync(0xffffffffu, sr0, m);
                pi = __shfl_xor_sync(0xffffffffu, si0, m);
                if (ctrl) { sr0 = pr; si0 = pi; }
                pr = __shfl_xor_sync(0xffffffffu, sr1, m);
                pi = __shfl_xor_sync(0xffffffffu, si1, m);
                if (ctrl) { sr1 = pr; si1 = pi; }
            }
        }
    }

    g_Wh[(2 * lane)            * 64 + w] = __float2half(sr0);
    g_Wh[(2 * lane + 1)        * 64 + w] = __float2half(si0);
    g_Wh[(2 * (lane + 32))     * 64 + w] = __float2half(sr1);
    g_Wh[(2 * (lane + 32) + 1) * 64 + w] = __float2half(si1);

    if (w == 0) {
        for (int s = 0; s < 2; s++) {
            int d = lane + 32 * s;
            float m[4];
            for (int c = 0; c < 4; c++) {
                float acc = 0.f;
                for (int i = 0; i < NQ; i++) {
                    int bit = (d >> (5 - i)) & 1;
                    acc += fc_w[c * NQ + i] * (bit ? -1.f : 1.f);
                }
                m[c] = acc;
            }
            g_Mt[d] = make_float4(m[0], m[1], m[2], m[3]);
        }
        if (lane == 0)
            g_fcb = make_float4(fc_b[0], fc_b[1], fc_b[2], fc_b[3]);
    }
}

// ============================================================================
// Kernel B: persistent, 256 thr = 8 independent warps, each M=16 rows x N=128.
// fp16 x-exact 2-block: y = (xh + xl) * wh.
// A: one LDG.128 per row per k16-chunk, straight into mma fragments via a
//    k-permutation (slots {2q,2q+1,2q+8,2q+9} <-> cols {4q..4q+3}); B smem is
//    staged with the matching permuted k-layout, so no shuffles are needed.
// No synchronization of any kind inside the tile loop.
// ============================================================================
#define STRIDE_B 144                          // 128B data + 16B pad, conflict-free
#define OF_MT   0                             // 64 float4 = 1 KB
#define OF_B    1024
#define SMEM_BYTES (OF_B + 128 * STRIDE_B)    // 1024 + 18432 = 19456

__global__ void __launch_bounds__(256, 2)
qnn_main(const float4* __restrict__ X, float4* __restrict__ out, int ntiles) {
    extern __shared__ char smc[];
    const uint32_t sm = smem_u32(smc);
    const int tid = threadIdx.x, wid = tid >> 5, lane = tid & 31;

    // ---- one-time staging: B[wrow][kpos] = Wh[wrow][colmap(kpos)] ----
    // colmap: within each k16 chunk, slot s -> col 4*((s&7)>>1) + 2*((s>>3)&1) + (s&1)
    for (int idx = tid; idx < 128 * 64; idx += 256) {
        int wrow = idx >> 6, kpos = idx & 63;
        int col = (kpos & ~15) + 4 * ((kpos & 7) >> 1) + 2 * ((kpos >> 3) & 1) + (kpos & 1);
        __half v = g_Wh[wrow * 64 + col];
        *reinterpret_cast<__half*>(smc + OF_B + wrow * STRIDE_B + kpos * 2) = v;
    }
    if (tid < 64) reinterpret_cast<float4*>(smc + OF_MT)[tid] = g_Mt[tid];
    const float4 fcb = g_fcb;
    __syncthreads();

    const int m0 = wid * 16;              // rows m0 .. m0+15
    const int r0 = m0 + (lane >> 2);      // this thread's rows: r0, r0+8
    const int l4 = lane & 3;

    // ldsm x4 base: b[0]={n0-7,k0-7} b[1]={n0-7,k8-15} b[2]={n8-15,k0-7} b[3]={n8-15,k8-15}
    const uint32_t bB = sm + OF_B
        + (uint32_t)(((lane >> 4) & 1) * 8 + (lane & 7)) * STRIDE_B
        + ((lane >> 3) & 1) * 16;

    const float4* sMt = reinterpret_cast<const float4*>(smc + OF_MT);

    for (int t = blockIdx.x; t < ntiles; t += gridDim.x) {
        const int rowbase = t * TILE;

        float c[16][4];                  // [n8 group][quad]
        #pragma unroll
        for (int j = 0; j < 16; j++)
            #pragma unroll
            for (int q = 0; q < 4; q++) c[j][q] = 0.f;
        float ss0 = 0.f, ss1 = 0.f;      // sumsq rows r0, r0+8

        #pragma unroll
        for (int kc = 0; kc < 4; kc++) {
            // ---- A fragments: one float4 per row covers this k16 chunk ----
            const int fi = l4 + 4 * kc;   // float4 index within row (16 per row)
            float4 v0 = X[(size_t)(rowbase + r0) * 16 + fi];
            float4 v1 = X[(size_t)(rowbase + r0 + 8) * 16 + fi];
            ss0 += v0.x * v0.x + v0.y * v0.y + v0.z * v0.z + v0.w * v0.w;
            ss1 += v1.x * v1.x + v1.y * v1.y + v1.z * v1.z + v1.w * v1.w;

            __half2 h00 = __floats2half2_rn(v0.x, v0.y);
            __half2 h01 = __floats2half2_rn(v0.z, v0.w);
            __half2 h10 = __floats2half2_rn(v1.x, v1.y);
            __half2 h11 = __floats2half2_rn(v1.z, v1.w);
            float2 f00 = __half22float2(h00), f01 = __half22float2(h01);
            float2 f10 = __half22float2(h10), f11 = __half22float2(h11);
            __half2 e00 = __floats2half2_rn(v0.x - f00.x, v0.y - f00.y);
            __half2 e01 = __floats2half2_rn(v0.z - f01.x, v0.w - f01.y);
            __half2 e10 = __floats2half2_rn(v1.x - f10.x, v1.y - f10.y);
            __half2 e11 = __floats2half2_rn(v1.z - f11.x, v1.w - f11.y);

            uint32_t ah[4], al[4];
            ah[0] = *reinterpret_cast<uint32_t*>(&h00);   // slots (2l4, 2l4+1)   row r0
            ah[1] = *reinterpret_cast<uint32_t*>(&h10);   //                      row r0+8
            ah[2] = *reinterpret_cast<uint32_t*>(&h01);   // slots (2l4+8, 2l4+9) row r0
            ah[3] = *reinterpret_cast<uint32_t*>(&h11);   //                      row r0+8
            al[0] = *reinterpret_cast<uint32_t*>(&e00);
            al[1] = *reinterpret_cast<uint32_t*>(&e10);
            al[2] = *reinterpret_cast<uint32_t*>(&e01);
            al[3] = *reinterpret_cast<uint32_t*>(&e11);

            // ---- full N=128: 8 n16 groups; each B frag feeds xh and xl MMAs ----
            #pragma unroll
            for (int pr = 0; pr < 8; pr++) {
                uint32_t b[4];
                ldsm_x4(b, bB + (uint32_t)(pr * 16) * STRIDE_B + kc * 32);
                mma16816(c[pr * 2],     ah, b);
                mma16816(c[pr * 2 + 1], ah, b + 2);
                mma16816(c[pr * 2],     al, b);
                mma16816(c[pr * 2 + 1], al, b + 2);
            }
        }

        // ---- row norms (quad reduce) ----
        ss0 += __shfl_xor_sync(0xffffffffu, ss0, 1);
        ss0 += __shfl_xor_sync(0xffffffffu, ss0, 2);
        ss1 += __shfl_xor_sync(0xffffffffu, ss1, 1);
        ss1 += __shfl_xor_sync(0xffffffffu, ss1, 2);

        // ---- epilogue: p = re^2 + im^2 ; 4-class dot against Mt ----
        float a0[4] = {0.f, 0.f, 0.f, 0.f}, a1[4] = {0.f, 0.f, 0.f, 0.f};
        #pragma unroll
        for (int j = 0; j < 16; j++) {
            const int amp = j * 4 + l4;
            float4 mt = sMt[amp];
            float p0 = c[j][0] * c[j][0] + c[j][1] * c[j][1];
            float p1 = c[j][2] * c[j][2] + c[j][3] * c[j][3];
            a0[0] += mt.x * p0; a0[1] += mt.y * p0; a0[2] += mt.z * p0; a0[3] += mt.w * p0;
            a1[0] += mt.x * p1; a1[1] += mt.y * p1; a1[2] += mt.z * p1; a1[3] += mt.w * p1;
        }
        #pragma unroll
        for (int q = 0; q < 4; q++) {
            a0[q] += __shfl_xor_sync(0xffffffffu, a0[q], 1);
            a0[q] += __shfl_xor_sync(0xffffffffu, a0[q], 2);
            a1[q] += __shfl_xor_sync(0xffffffffu, a1[q], 1);
            a1[q] += __shfl_xor_sync(0xffffffffu, a1[q], 2);
        }

        if (l4 == 0) {
            float inv0 = 1.f / fmaxf(ss0, 1e-24f);
            float inv1 = 1.f / fmaxf(ss1, 1e-24f);
            float4 r;
            r.x = a0[0] * inv0 + fcb.x;
            r.y = a0[1] * inv0 + fcb.y;
            r.z = a0[2] * inv0 + fcb.z;
            r.w = a0[3] * inv0 + fcb.w;
            out[rowbase + r0] = r;
            r.x = a1[0] * inv1 + fcb.x;
            r.y = a1[1] * inv1 + fcb.y;
            r.z = a1[2] * inv1 + fcb.z;
            r.w = a1[3] * inv1 + fcb.w;
            out[rowbase + r0 + 8] = r;
        }
    }
}

// ============================================================================
// Launch
// ============================================================================
extern "C" void kernel_launch(void* const* d_in, const int* in_sizes, int n_in,
                              void* d_out, int out_size) {
    const float* x    = (const float*)d_in[0];
    const float* wts  = (const float*)d_in[1];
    const float* fc_w = (const float*)d_in[2];
    const float* fc_b = (const float*)d_in[3];

    int n_items = in_sizes[0] / DIM;   // 262144
    int ntiles  = n_items / TILE;      // 2048

    qnn_build<<<DIM, 32>>>(wts, fc_w, fc_b);
    qnn_main<<<GRIDB, 256, SMEM_BYTES>>>((const float4*)x, (float4*)d_out, ntiles);
}

// round 11
// speedup vs baseline: 2.1664x; 1.1530x over previous
#include <cuda_runtime.h>
#include <cuda_fp16.h>
#include <cstdint>

// ============================================================================
// Problem constants
// ============================================================================
#define NQ     6
#define DIM    64
#define NL     8
#define TILE   128           // batch rows per tile (8 warps x 16 rows)
#define GRIDB  296           // persistent CTAs (148 SMs x 2)

// Circuit constants built per-launch by qnn_build.
// W row 2a = Re(U[a][:]), row 2a+1 = Im(U[a][:]), fp16, 64 cols.
__device__ __align__(16) __half g_Wh[128 * 64];
__device__ __align__(16) float4 g_Mt[64];   // Mt[a] = {M[0][a],..,M[3][a]}, M = fc_w * Zsign^T
__device__ __align__(16) float4 g_fcb;

// ============================================================================
// PTX helpers (plain sm_103-legal)
// ============================================================================
__device__ __forceinline__ uint32_t smem_u32(const void* p) {
    uint32_t a;
    asm("{ .reg .u64 t; cvta.to.shared.u64 t, %1; cvt.u32.u64 %0, t; }" : "=r"(a) : "l"(p));
    return a;
}
__device__ __forceinline__ void ldsm_x4(uint32_t* r, uint32_t addr) {
    asm volatile("ldmatrix.sync.aligned.m8n8.x4.shared.b16 {%0,%1,%2,%3}, [%4];"
                 : "=r"(r[0]), "=r"(r[1]), "=r"(r[2]), "=r"(r[3]) : "r"(addr));
}
__device__ __forceinline__ void mma16816(float* c, const uint32_t* a, const uint32_t* b) {
    asm volatile("mma.sync.aligned.m16n8k16.row.col.f32.f16.f16.f32 "
                 "{%0,%1,%2,%3}, {%4,%5,%6,%7}, {%8,%9}, {%0,%1,%2,%3};"
                 : "+f"(c[0]), "+f"(c[1]), "+f"(c[2]), "+f"(c[3])
                 : "r"(a[0]), "r"(a[1]), "r"(a[2]), "r"(a[3]), "r"(b[0]), "r"(b[1]));
}

// ============================================================================
// Kernel A: build U columns (one warp per basis column), emit Wh/Mt/fcb.
// Each lane holds 2 complex amplitudes: amp = lane + 32*slot.
// qubit q acts on amplitude-index bit b = 5-q (qubit 0 = MSB).
// ============================================================================
__global__ void qnn_build(const float* __restrict__ weights,
                          const float* __restrict__ fc_w,
                          const float* __restrict__ fc_b) {
    const int w = blockIdx.x;
    const int lane = threadIdx.x;

    float sr0 = (lane == w) ? 1.f : 0.f,      si0 = 0.f;
    float sr1 = (lane + 32 == w) ? 1.f : 0.f, si1 = 0.f;

    for (int l = 0; l < NL; l++) {
        for (int q = 0; q < NQ; q++) {
            const float* g = weights + (l * NQ + q) * 3;
            float phi = g[0], th = g[1], om = g[2];
            float st, ct; sincosf(0.5f * th, &st, &ct);
            float sa, ca; sincosf(0.5f * (phi + om), &sa, &ca);
            float sb, cb; sincosf(0.5f * (phi - om), &sb, &cb);
            float m00r =  ca * ct, m00i = -sa * ct;
            float m01r = -cb * st, m01i = -sb * st;
            float m10r =  cb * st, m10i = -sb * st;
            float m11r =  ca * ct, m11i =  sa * ct;
            int b = 5 - q;
            if (b == 5) {
                float nr0 = m00r*sr0 - m00i*si0 + m01r*sr1 - m01i*si1;
                float ni0 = m00r*si0 + m00i*sr0 + m01r*si1 + m01i*sr1;
                float nr1 = m10r*sr0 - m10i*si0 + m11r*sr1 - m11i*si1;
                float ni1 = m10r*si0 + m10i*sr0 + m11r*si1 + m11i*sr1;
                sr0 = nr0; si0 = ni0; sr1 = nr1; si1 = ni1;
            } else {
                int msk = 1 << b;
                int bit = (lane >> b) & 1;
                float dr = bit ? m11r : m00r, di = bit ? m11i : m00i;
                float orr = bit ? m10r : m01r, oi = bit ? m10i : m01i;
                float pr, pi, nr, ni;
                pr = __shfl_xor_sync(0xffffffffu, sr0, msk);
                pi = __shfl_xor_sync(0xffffffffu, si0, msk);
                nr = dr*sr0 - di*si0 + orr*pr - oi*pi;
                ni = dr*si0 + di*sr0 + orr*pi + oi*pr;
                sr0 = nr; si0 = ni;
                pr = __shfl_xor_sync(0xffffffffu, sr1, msk);
                pi = __shfl_xor_sync(0xffffffffu, si1, msk);
                nr = dr*sr1 - di*si1 + orr*pr - oi*pi;
                ni = dr*si1 + di*sr1 + orr*pi + oi*pr;
                sr1 = nr; si1 = ni;
            }
        }
        int r = (l % (NQ - 1)) + 1;
        for (int q = 0; q < NQ; q++) {
            int t = (q + r) % NQ;
            int bc = 5 - q, bt = 5 - t;
            if (bc == 5) {
                int m = 1 << bt;
                sr1 = __shfl_xor_sync(0xffffffffu, sr1, m);
                si1 = __shfl_xor_sync(0xffffffffu, si1, m);
            } else if (bt == 5) {
                if ((lane >> bc) & 1) {
                    float tmp;
                    tmp = sr0; sr0 = sr1; sr1 = tmp;
                    tmp = si0; si0 = si1; si1 = tmp;
                }
            } else {
                int m = 1 << bt;
                int ctrl = (lane >> bc) & 1;
                float pr, pi;
                pr = __shfl_xor_sync(0xffffffffu, sr0, m);
                pi = __shfl_xor_sync(0xffffffffu, si0, m);
                if (ctrl) { sr0 = pr; si0 = pi; }
                pr = __shfl_xor_sync(0xffffffffu, sr1, m);
                pi = __shfl_xor_sync(0xffffffffu, si1, m);
                if (ctrl) { sr1 = pr; si1 = pi; }
            }
        }
    }

    g_Wh[(2 * lane)            * 64 + w] = __float2half(sr0);
    g_Wh[(2 * lane + 1)        * 64 + w] = __float2half(si0);
    g_Wh[(2 * (lane + 32))     * 64 + w] = __float2half(sr1);
    g_Wh[(2 * (lane + 32) + 1) * 64 + w] = __float2half(si1);

    if (w == 0) {
        for (int s = 0; s < 2; s++) {
            int d = lane + 32 * s;
            float m[4];
            for (int c = 0; c < 4; c++) {
                float acc = 0.f;
                for (int i = 0; i < NQ; i++) {
                    int bit = (d >> (5 - i)) & 1;
                    acc += fc_w[c * NQ + i] * (bit ? -1.f : 1.f);
                }
                m[c] = acc;
            }
            g_Mt[d] = make_float4(m[0], m[1], m[2], m[3]);
        }
        if (lane == 0)
            g_fcb = make_float4(fc_b[0], fc_b[1], fc_b[2], fc_b[3]);
    }
}

// ============================================================================
// Kernel B: persistent, 256 thr = 8 independent warps, each M=16 rows x N=128.
// Pure fp16 GEMM: y = fp16(x) * wh  (error budget analysis: ~2.7e-4 total).
// A: one LDG.128 per row per k16-chunk straight into mma fragments via a
//    k-permutation (slots {2q,2q+1,2q+8,2q+9} <-> cols {4q..4q+3}); B smem is
//    staged with the matching permuted k-layout.
// Cross-tile software pipeline: next tile's X prefetched into registers while
// current tile computes.  No synchronization inside the tile loop.
// ============================================================================
#define STRIDE_B 144                          // 128B data + 16B pad, conflict-free
#define OF_MT   0                             // 64 float4 = 1 KB
#define OF_B    1024
#define SMEM_BYTES (OF_B + 128 * STRIDE_B)    // 1024 + 18432 = 19456

__global__ void __launch_bounds__(256, 2)
qnn_main(const float4* __restrict__ X, float4* __restrict__ out, int ntiles) {
    extern __shared__ char smc[];
    const uint32_t sm = smem_u32(smc);
    const int tid = threadIdx.x, wid = tid >> 5, lane = tid & 31;

    // ---- one-time staging: B[wrow][kpos] = Wh[wrow][colmap(kpos)] ----
    // colmap: within each k16 chunk, slot s -> col 4*((s&7)>>1) + 2*((s>>3)&1) + (s&1)
    for (int idx = tid; idx < 128 * 64; idx += 256) {
        int wrow = idx >> 6, kpos = idx & 63;
        int col = (kpos & ~15) + 4 * ((kpos & 7) >> 1) + 2 * ((kpos >> 3) & 1) + (kpos & 1);
        __half v = g_Wh[wrow * 64 + col];
        *reinterpret_cast<__half*>(smc + OF_B + wrow * STRIDE_B + kpos * 2) = v;
    }
    if (tid < 64) reinterpret_cast<float4*>(smc + OF_MT)[tid] = g_Mt[tid];
    const float4 fcb = g_fcb;
    __syncthreads();

    const int m0 = wid * 16;              // rows m0 .. m0+15
    const int r0 = m0 + (lane >> 2);      // this thread's rows: r0, r0+8
    const int l4 = lane & 3;

    // ldsm x4 base: b[0]={n0-7,k0-7} b[1]={n0-7,k8-15} b[2]={n8-15,k0-7} b[3]={n8-15,k8-15}
    const uint32_t bB = sm + OF_B
        + (uint32_t)(((lane >> 4) & 1) * 8 + (lane & 7)) * STRIDE_B
        + ((lane >> 3) & 1) * 16;

    const float4* sMt = reinterpret_cast<const float4*>(smc + OF_MT);

    // per-thread gmem offsets (float4 units)
    const size_t o0 = (size_t)r0 * 16 + l4;        // + 4*kc ; row r0
    const size_t o1 = (size_t)(r0 + 8) * 16 + l4;  //         row r0+8

    // ---- prologue: prefetch first tile ----
    float4 pv[8];
    {
        const size_t tb = (size_t)blockIdx.x * TILE * 16;
        #pragma unroll
        for (int kc = 0; kc < 4; kc++) {
            pv[kc * 2]     = X[tb + o0 + 4 * kc];
            pv[kc * 2 + 1] = X[tb + o1 + 4 * kc];
        }
    }

    for (int t = blockIdx.x; t < ntiles; t += gridDim.x) {
        const int rowbase = t * TILE;

        // ---- issue next tile's loads early (overlap with compute below) ----
        float4 nv[8];
        {
            const int tn = (t + gridDim.x < ntiles) ? (t + gridDim.x) : t;
            const size_t tb = (size_t)tn * TILE * 16;
            #pragma unroll
            for (int kc = 0; kc < 4; kc++) {
                nv[kc * 2]     = X[tb + o0 + 4 * kc];
                nv[kc * 2 + 1] = X[tb + o1 + 4 * kc];
            }
        }

        float c[16][4];                  // [n8 group][quad]
        #pragma unroll
        for (int j = 0; j < 16; j++)
            #pragma unroll
            for (int q = 0; q < 4; q++) c[j][q] = 0.f;
        float ss0 = 0.f, ss1 = 0.f;      // sumsq rows r0, r0+8

        #pragma unroll
        for (int kc = 0; kc < 4; kc++) {
            // ---- A fragments from prefetched registers ----
            float4 v0 = pv[kc * 2];
            float4 v1 = pv[kc * 2 + 1];
            ss0 += v0.x * v0.x + v0.y * v0.y + v0.z * v0.z + v0.w * v0.w;
            ss1 += v1.x * v1.x + v1.y * v1.y + v1.z * v1.z + v1.w * v1.w;

            __half2 h00 = __floats2half2_rn(v0.x, v0.y);
            __half2 h01 = __floats2half2_rn(v0.z, v0.w);
            __half2 h10 = __floats2half2_rn(v1.x, v1.y);
            __half2 h11 = __floats2half2_rn(v1.z, v1.w);

            uint32_t ah[4];
            ah[0] = *reinterpret_cast<uint32_t*>(&h00);   // slots (2l4, 2l4+1)   row r0
            ah[1] = *reinterpret_cast<uint32_t*>(&h10);   //                      row r0+8
            ah[2] = *reinterpret_cast<uint32_t*>(&h01);   // slots (2l4+8, 2l4+9) row r0
            ah[3] = *reinterpret_cast<uint32_t*>(&h11);   //                      row r0+8

            // ---- full N=128: 8 n16 groups ----
            #pragma unroll
            for (int pr = 0; pr < 8; pr++) {
                uint32_t b[4];
                ldsm_x4(b, bB + (uint32_t)(pr * 16) * STRIDE_B + kc * 32);
                mma16816(c[pr * 2],     ah, b);
                mma16816(c[pr * 2 + 1], ah, b + 2);
            }
        }

        // ---- row norms (quad reduce) ----
        ss0 += __shfl_xor_sync(0xffffffffu, ss0, 1);
        ss0 += __shfl_xor_sync(0xffffffffu, ss0, 2);
        ss1 += __shfl_xor_sync(0xffffffffu, ss1, 1);
        ss1 += __shfl_xor_sync(0xffffffffu, ss1, 2);

        // ---- epilogue: p = re^2 + im^2 ; 4-class dot against Mt ----
        float a0[4] = {0.f, 0.f, 0.f, 0.f}, a1[4] = {0.f, 0.f, 0.f, 0.f};
        #pragma unroll
        for (int j = 0; j < 16; j++) {
            const int amp = j * 4 + l4;
            float4 mt = sMt[amp];
            float p0 = c[j][0] * c[j][0] + c[j][1] * c[j][1];
            float p1 = c[j][2] * c[j][2] + c[j][3] * c[j][3];
            a0[0] += mt.x * p0; a0[1] += mt.y * p0; a0[2] += mt.z * p0; a0[3] += mt.w * p0;
            a1[0] += mt.x * p1; a1[1] += mt.y * p1; a1[2] += mt.z * p1; a1[3] += mt.w * p1;
        }
        #pragma unroll
        for (int q = 0; q < 4; q++) {
            a0[q] += __shfl_xor_sync(0xffffffffu, a0[q], 1);
            a0[q] += __shfl_xor_sync(0xffffffffu, a0[q], 2);
            a1[q] += __shfl_xor_sync(0xffffffffu, a1[q], 1);
            a1[q] += __shfl_xor_sync(0xffffffffu, a1[q], 2);
        }

        if (l4 == 0) {
            float inv0 = 1.f / fmaxf(ss0, 1e-24f);
            float inv1 = 1.f / fmaxf(ss1, 1e-24f);
            float4 r;
            r.x = a0[0] * inv0 + fcb.x;
            r.y = a0[1] * inv0 + fcb.y;
            r.z = a0[2] * inv0 + fcb.z;
            r.w = a0[3] * inv0 + fcb.w;
            out[rowbase + r0] = r;
            r.x = a1[0] * inv1 + fcb.x;
            r.y = a1[1] * inv1 + fcb.y;
            r.z = a1[2] * inv1 + fcb.z;
            r.w = a1[3] * inv1 + fcb.w;
            out[rowbase + r0 + 8] = r;
        }

        // ---- rotate prefetch buffer ----
        #pragma unroll
        for (int i = 0; i < 8; i++) pv[i] = nv[i];
    }
}

// ============================================================================
// Launch
// ============================================================================
extern "C" void kernel_launch(void* const* d_in, const int* in_sizes, int n_in,
                              void* d_out, int out_size) {
    const float* x    = (const float*)d_in[0];
    const float* wts  = (const float*)d_in[1];
    const float* fc_w = (const float*)d_in[2];
    const float* fc_b = (const float*)d_in[3];

    int n_items = in_sizes[0] / DIM;   // 262144
    int ntiles  = n_items / TILE;      // 2048

    qnn_build<<<DIM, 32>>>(wts, fc_w, fc_b);
    qnn_main<<<GRIDB, 256, SMEM_BYTES>>>((const float4*)x, (float4*)d_out, ntiles);
}